// round 16
// baseline (speedup 1.0000x reference)
#include <cuda_runtime.h>
#include <math.h>

#define HW    4096
#define DM    64
#define DS    16
#define NB    4

// Scratch (device globals; no allocation allowed)
__device__ float g_h[64];
__device__ float g_part[1024];        // 512 stat blocks x (sum, sumsq)
__device__ float g_wT[16 * 3528];     // transposed weights [chunk][icl*9+tap][98]
__device__ float g_delta[NB*DM*HW];   // 4MB
__device__ float g_Bval[NB*DS*HW];    // 1MB
__device__ float g_Cval[NB*DS*HW];    // 1MB

typedef unsigned long long ull;

__device__ __forceinline__ ull pk2(float x) {
    ull r; asm("mov.b64 %0,{%1,%1};" : "=l"(r) : "f"(x)); return r;
}
__device__ __forceinline__ ull pk(float lo, float hi) {
    ull r; asm("mov.b64 %0,{%1,%2};" : "=l"(r) : "f"(lo), "f"(hi)); return r;
}
__device__ __forceinline__ void fma2(ull &a, ull b, ull c) {
    asm("fma.rn.f32x2 %0,%1,%2,%0;" : "+l"(a) : "l"(b), "l"(c));
}
__device__ __forceinline__ float2 up2(ull a) {
    float2 v; asm("mov.b64 {%0,%1},%2;" : "=f"(v.x), "=f"(v.y) : "l"(a)); return v;
}

// ---------------------------------------------------------------------------
// K0 (fused prep): blocks 0..511 = GroupNorm partial sums;
// blocks 512..732 = weight transpose (+ h table in block 512).
// ---------------------------------------------------------------------------
__global__ void __launch_bounds__(256) k_prep(
        const float* __restrict__ u,
        const float* __restrict__ wd,
        const float* __restrict__ wB,
        const float* __restrict__ wC) {
    int blk = blockIdx.x;
    if (blk < 512) {
        int bg = blk >> 5, seg = blk & 31;
        const float4* base = (const float4*)(u + bg * 65536 + seg * 2048);
        float s = 0.f, s2 = 0.f;
        #pragma unroll
        for (int i = threadIdx.x; i < 512; i += 256) {
            float4 v = base[i];
            s += v.x + v.y + v.z + v.w;
            s2 = fmaf(v.x, v.x, s2); s2 = fmaf(v.y, v.y, s2);
            s2 = fmaf(v.z, v.z, s2); s2 = fmaf(v.w, v.w, s2);
        }
        for (int o = 16; o; o >>= 1) {
            s  += __shfl_down_sync(0xFFFFFFFFu, s,  o);
            s2 += __shfl_down_sync(0xFFFFFFFFu, s2, o);
        }
        __shared__ float ss[8], ss2[8];
        int w = threadIdx.x >> 5, l = threadIdx.x & 31;
        if (l == 0) { ss[w] = s; ss2[w] = s2; }
        __syncthreads();
        if (threadIdx.x == 0) {
            float S = 0.f, S2 = 0.f;
            #pragma unroll
            for (int i = 0; i < 8; i++) { S += ss[i]; S2 += ss2[i]; }
            g_part[blk * 2]     = S;
            g_part[blk * 2 + 1] = S2;
        }
    } else {
        int wb = blk - 512;
        if (wb == 0 && threadIdx.x < 64) {
            int n = threadIdx.x;
            double acc = 0.0;
            for (int m = 1; m < 32; m++) {
                double km = 2.0 * 3.141592653589793238 * (double)m / 64.0;
                acc += km * sin(km * (double)n);
            }
            g_h[n] = (float)(-acc * 2.0 / 64.0);
        }
        int idx = wb * 256 + threadIdx.x;
        if (idx >= 16 * 3528) return;
        int chunk = idx / 3528;
        int r2 = idx - chunk * 3528;
        int row = r2 / 98;            // icl*9 + tap
        int oc  = r2 - row * 98;
        int icl = row / 9, tap = row - icl * 9;
        int ic  = chunk * 4 + icl;
        float v = 0.f;
        if (oc < 64)      v = wd[oc * 576 + ic * 9 + tap];
        else if (oc < 80) v = wB[(oc - 64) * 576 + ic * 9 + tap];
        else if (oc < 96) v = wC[(oc - 80) * 576 + ic * 9 + tap];
        g_wT[idx] = v;
    }
}

// ---------------------------------------------------------------------------
// K2: fused GroupNorm + circular 3x3 convs (R13 version, frozen).
// ---------------------------------------------------------------------------
__global__ void __launch_bounds__(128, 4) k_conv(
        const float* __restrict__ u,
        const float* __restrict__ gamma, const float* __restrict__ beta,
        const float* __restrict__ bd, const float* __restrict__ dtp) {
    __shared__ float ws2[2][3528];       // 28.2KB [buf][(icl*9+tap)*98 + oc]
    __shared__ float xs2[2][408];        // 3.3KB  [buf][(icl*3+rr)*34 + j]
    __shared__ float cs_scale[64], cs_shift[64];

    int bx = blockIdx.x;
    int b  = bx >> 7;
    int t  = bx & 127;
    int y  = t >> 1;
    int x0 = (t & 1) * 32;

    int tid = threadIdx.x;
    int ocg = tid >> 3;            // 0..15
    int pxg = tid & 7;             // 0..7
    int oc0 = ocg * 6;
    int px0 = pxg * 4;

    if (tid < 64) {
        int bg = b * 4 + (tid >> 4);
        float S = 0.f, S2 = 0.f;
        #pragma unroll
        for (int i = 0; i < 32; i++) {
            S  += g_part[(bg * 32 + i) * 2];
            S2 += g_part[(bg * 32 + i) * 2 + 1];
        }
        float mu  = S  * (1.f / 65536.f);
        float var = S2 * (1.f / 65536.f) - mu * mu;
        float rs = rsqrtf(var + 1e-5f) * gamma[tid];
        cs_scale[tid] = rs;
        cs_shift[tid] = beta[tid] - mu * rs;
    }
    __syncthreads();

    int s_row[4], s_j[4], s_icl[4], s_gy[4], s_gx[4];
    bool s_ok[4];
    #pragma unroll
    for (int s = 0; s < 4; s++) {
        int idx = tid + 128 * s;
        s_ok[s] = idx < 408;
        int row = idx / 34;
        int j   = idx - row * 34;
        if (!s_ok[s]) { row = 0; j = 0; }
        int icl = row / 3;
        int rr  = row - icl * 3;
        s_row[s] = row; s_j[s] = j; s_icl[s] = icl;
        s_gy[s] = (y + rr - 1) & 63;
        s_gx[s] = (x0 - 1 + j) & 63;
    }

    unsigned ws_sm = (unsigned)__cvta_generic_to_shared(ws2);

    {
        const float4* wsrc = (const float4*)g_wT;
        #pragma unroll
        for (int s = 0; s < 7; s++) {
            int i = tid + 128 * s;
            if (i < 882) {
                unsigned dst = ws_sm + i * 16;
                asm volatile("cp.async.cg.shared.global [%0], [%1], 16;"
                             :: "r"(dst), "l"(wsrc + i));
            }
        }
        asm volatile("cp.async.commit_group;");
    }
    {
        #pragma unroll
        for (int s = 0; s < 4; s++) {
            if (s_ok[s]) {
                int ic = s_icl[s];
                float v = u[((b * 64 + ic) * 64 + s_gy[s]) * 64 + s_gx[s]];
                xs2[0][s_row[s] * 34 + s_j[s]] = fmaf(v, cs_scale[ic], cs_shift[ic]);
            }
        }
    }
    asm volatile("cp.async.wait_group 0;");
    __syncthreads();

    ull acc[3][4];
    #pragma unroll
    for (int p = 0; p < 3; p++)
        #pragma unroll
        for (int q = 0; q < 4; q++) acc[p][q] = 0ull;

    #pragma unroll 1
    for (int c = 0; c < 16; c++) {
        float xstage[4];
        if (c < 15) {
            const float4* wsrc = (const float4*)g_wT + (c + 1) * 882;
            unsigned wdst = ws_sm + ((c + 1) & 1) * 14112;
            #pragma unroll
            for (int s = 0; s < 7; s++) {
                int i = tid + 128 * s;
                if (i < 882) {
                    asm volatile("cp.async.cg.shared.global [%0], [%1], 16;"
                                 :: "r"(wdst + i * 16), "l"(wsrc + i));
                }
            }
            asm volatile("cp.async.commit_group;");
            #pragma unroll
            for (int s = 0; s < 4; s++) {
                if (s_ok[s]) {
                    int ic = (c + 1) * 4 + s_icl[s];
                    float v = u[((b * 64 + ic) * 64 + s_gy[s]) * 64 + s_gx[s]];
                    xstage[s] = fmaf(v, cs_scale[ic], cs_shift[ic]);
                }
            }
        }

        const float* wsb = ws2[c & 1];
        const float* xsb = xs2[c & 1];
        #pragma unroll
        for (int icl = 0; icl < 4; icl++) {
            const float* xp = xsb + icl * 102 + px0;
            ull P[3][6];
            #pragma unroll
            for (int rr = 0; rr < 3; rr++) {
                float2 p0 = *(const float2*)(xp + rr * 34);
                float2 p1 = *(const float2*)(xp + rr * 34 + 2);
                float2 p2 = *(const float2*)(xp + rr * 34 + 4);
                P[rr][0] = pk2(p0.x); P[rr][1] = pk2(p0.y);
                P[rr][2] = pk2(p1.x); P[rr][3] = pk2(p1.y);
                P[rr][4] = pk2(p2.x); P[rr][5] = pk2(p2.y);
            }
            #pragma unroll
            for (int dy = 0; dy < 3; dy++) {
                #pragma unroll
                for (int dx = 0; dx < 3; dx++) {
                    const float* row = wsb + (icl * 9 + dy * 3 + dx) * 98 + oc0;
                    ull w01 = *(const ull*)(row);
                    ull w23 = *(const ull*)(row + 2);
                    ull w45 = *(const ull*)(row + 4);
                    ull pa = P[dy][dx];
                    ull pb = P[dy][dx + 1];
                    ull pc = P[dy][dx + 2];
                    ull pd = P[dy][dx + 3];
                    fma2(acc[0][0], w01, pa); fma2(acc[0][1], w01, pb);
                    fma2(acc[0][2], w01, pc); fma2(acc[0][3], w01, pd);
                    fma2(acc[1][0], w23, pa); fma2(acc[1][1], w23, pb);
                    fma2(acc[1][2], w23, pc); fma2(acc[1][3], w23, pd);
                    fma2(acc[2][0], w45, pa); fma2(acc[2][1], w45, pb);
                    fma2(acc[2][2], w45, pc); fma2(acc[2][3], w45, pd);
                }
            }
        }

        if (c < 15) {
            float* xdst = xs2[(c + 1) & 1];
            #pragma unroll
            for (int s = 0; s < 4; s++)
                if (s_ok[s]) xdst[s_row[s] * 34 + s_j[s]] = xstage[s];
            asm volatile("cp.async.wait_group 0;");
        }
        __syncthreads();
    }

    float dtv = __ldg(dtp);
    int pbase = y * 64 + x0 + px0;

    #pragma unroll
    for (int p = 0; p < 3; p++) {
        #pragma unroll
        for (int half = 0; half < 2; half++) {
            int oc = oc0 + 2 * p + half;
            float av[4];
            #pragma unroll
            for (int q = 0; q < 4; q++) {
                float2 v = up2(acc[p][q]);
                av[q] = half ? v.y : v.x;
            }
            if (oc < 64) {
                float bias = bd[oc] + dtv;
                float4 o4;
                float* pv = &o4.x;
                #pragma unroll
                for (int q = 0; q < 4; q++) {
                    float v = av[q] + bias;
                    float sp = (v > 0.f) ? (v + log1pf(expf(-v))) : log1pf(expf(v));
                    pv[q] = fminf(fmaxf(sp, 1e-4f), 5.0f);
                }
                *(float4*)(g_delta + (b * 64 + oc) * HW + pbase) = o4;
            } else if (oc < 80) {
                *(float4*)(g_Bval + (b * 16 + (oc - 64)) * HW + pbase) =
                    make_float4(av[0], av[1], av[2], av[3]);
            } else {
                *(float4*)(g_Cval + (b * 16 + (oc - 80)) * HW + pbase) =
                    make_float4(av[0], av[1], av[2], av[3]);
            }
        }
    }
}

// ---------------------------------------------------------------------------
// K3: circulant matmuls with cp.async-pipelined state reads.
// 6 blocks/SM (regs forced <=85; smem 34.4KB x6 = 206KB fits).
// ---------------------------------------------------------------------------
__global__ void __launch_bounds__(128, 6) k_update(
        const float* __restrict__ u, const float* __restrict__ sprev,
        const float* __restrict__ logA, float* __restrict__ out) {
    __shared__ float Xs[64 * 68];    // X[r][c] at r*68 + c + 2*(c>>5)  17.4KB
    __shared__ float Ms[4096];       // staging: mx then my             16KB
    __shared__ float hb[144];        // h[i mod 64]

    int tid = threadIdx.x;
    int bp  = blockIdx.x;            // b*1024 + d*16 + n
    int b = bp >> 10, d = (bp >> 4) & 63, n = bp & 15;

    int p0 = (((b * 3 + 0) * 64 + d) * 16 + n) * HW;
    int p1 = p0 + 64 * 16 * HW;
    int p2 = p1 + 64 * 16 * HW;
    const float4* m0p4 = (const float4*)(sprev + p0);

    unsigned ms_sm = (unsigned)__cvta_generic_to_shared(Ms);

    {
        const float4* mxp = (const float4*)(sprev + p1);
        #pragma unroll
        for (int s = 0; s < 8; s++) {
            int i = tid + 128 * s;
            asm volatile("cp.async.cg.shared.global [%0], [%1], 16;"
                         :: "r"(ms_sm + i * 16), "l"(mxp + i));
        }
        asm volatile("cp.async.commit_group;");
    }

    #pragma unroll
    for (int s = 0; s < 8; s++) {
        int l4 = tid + 128 * s;              // < 1024
        float4 v = m0p4[l4];
        int idx = l4 * 4;
        int r = idx >> 6, cc = idx & 63;
        float* xsp = &Xs[r * 68 + cc + 2 * (cc >> 5)];
        *(float2*)xsp       = make_float2(v.x, v.y);
        *(float2*)(xsp + 2) = make_float2(v.z, v.w);
    }
    for (int i = tid; i < 144; i += 128) hb[i] = g_h[i & 63];
    __syncthreads();

    float Ad = -expf(__ldg(&logA[d * 16 + n]));
    int off_bd = (b * 64 + d) * HW;
    int off_bn = (b * 16 + n) * HW;
    const int so = NB * DM * HW;

    // ===== Phase 1: Gx[r][c] = sum_k X[r][k] h[c-k], 4 rows x 8 cols =====
    {
        int rg = tid >> 3, cg = tid & 7;    // rg 0..15, cg 0..7
        int r0 = rg * 4, c0 = cg * 8;
        int gap2 = 2 * (c0 >> 5);

        ull a[2][8];
        #pragma unroll
        for (int p = 0; p < 2; p++)
            #pragma unroll
            for (int j = 0; j < 8; j++) a[p][j] = 0ull;

        #pragma unroll 1
        for (int k8 = 0; k8 < 64; k8 += 8) {
            ull hl[15];
            int hbase = c0 - k8 + 57;       // in [1,113]
            #pragma unroll
            for (int m = 0; m < 15; m++) hl[m] = pk2(hb[hbase + m]);
            int gk = 2 * (k8 >> 5);
            #pragma unroll
            for (int kk2 = 0; kk2 < 4; kk2++) {
                int xo = k8 + kk2 * 2 + gk;     // even, no gap crossing
                float2 xr0 = *(const float2*)&Xs[(r0 + 0) * 68 + xo];
                float2 xr1 = *(const float2*)&Xs[(r0 + 1) * 68 + xo];
                float2 xr2 = *(const float2*)&Xs[(r0 + 2) * 68 + xo];
                float2 xr3 = *(const float2*)&Xs[(r0 + 3) * 68 + xo];
                {   // kk = 2*kk2
                    int kk = kk2 * 2;
                    ull x01 = pk(xr0.x, xr1.x), x23 = pk(xr2.x, xr3.x);
                    #pragma unroll
                    for (int j = 0; j < 8; j++) {
                        fma2(a[0][j], x01, hl[j - kk + 7]);
                        fma2(a[1][j], x23, hl[j - kk + 7]);
                    }
                }
                {   // kk = 2*kk2+1
                    int kk = kk2 * 2 + 1;
                    ull x01 = pk(xr0.y, xr1.y), x23 = pk(xr2.y, xr3.y);
                    #pragma unroll
                    for (int j = 0; j < 8; j++) {
                        fma2(a[0][j], x01, hl[j - kk + 7]);
                        fma2(a[1][j], x23, hl[j - kk + 7]);
                    }
                }
            }
        }

        asm volatile("cp.async.wait_group 0;");
        __syncthreads();

        #pragma unroll
        for (int i = 0; i < 4; i++) {
            int row = r0 + i;
            int off = row * 64 + c0;
            float4 dv0 = *(const float4*)(g_delta + off_bd + off);
            float4 dv1 = *(const float4*)(g_delta + off_bd + off + 4);
            float4 uv0 = *(const float4*)(u + off_bd + off);
            float4 uv1 = *(const float4*)(u + off_bd + off + 4);
            float4 bv0 = *(const float4*)(g_Bval + off_bn + off);
            float4 bv1 = *(const float4*)(g_Bval + off_bn + off + 4);
            float4 mx0 = *(const float4*)&Ms[off];
            float4 mx1 = *(const float4*)&Ms[off + 4];
            float dd[8] = { dv0.x, dv0.y, dv0.z, dv0.w, dv1.x, dv1.y, dv1.z, dv1.w };
            float uu[8] = { uv0.x, uv0.y, uv0.z, uv0.w, uv1.x, uv1.y, uv1.z, uv1.w };
            float bb[8] = { bv0.x, bv0.y, bv0.z, bv0.w, bv1.x, bv1.y, bv1.z, bv1.w };
            float mx[8] = { mx0.x, mx0.y, mx0.z, mx0.w, mx1.x, mx1.y, mx1.z, mx1.w };
            float m0n[8], mxn[8];
            #pragma unroll
            for (int j = 0; j < 8; j++) {
                float2 tt = up2(a[i >> 1][j]);
                float gx = (i & 1) ? tt.y : tt.x;
                float m0v = Xs[row * 68 + c0 + j + gap2];
                float Ab = __expf(dd[j] * Ad);
                m0n[j] = fmaf(Ab, m0v, dd[j] * bb[j] * uu[j]);
                mxn[j] = Ab * (mx[j] - gx);
            }
            *(float4*)(out + so + p0 + off)     = make_float4(m0n[0], m0n[1], m0n[2], m0n[3]);
            *(float4*)(out + so + p0 + off + 4) = make_float4(m0n[4], m0n[5], m0n[6], m0n[7]);
            *(float4*)(out + so + p1 + off)     = make_float4(mxn[0], mxn[1], mxn[2], mxn[3]);
            *(float4*)(out + so + p1 + off + 4) = make_float4(mxn[4], mxn[5], mxn[6], mxn[7]);
        }
    }

    __syncthreads();
    {
        const float4* myp = (const float4*)(sprev + p2);
        #pragma unroll
        for (int s = 0; s < 8; s++) {
            int i = tid + 128 * s;
            asm volatile("cp.async.cg.shared.global [%0], [%1], 16;"
                         :: "r"(ms_sm + i * 16), "l"(myp + i));
        }
        asm volatile("cp.async.commit_group;");
    }

    // ===== Phase 2: Gy[r][c] = sum_k h[r-k] X[k][c], 8 rows x 4 cols =====
    {
        int rg2 = tid >> 4, cg2 = tid & 15;   // rg2 0..7, cg2 0..15
        int r0 = rg2 * 8, c0 = cg2 * 4;
        int gapc = 2 * (c0 >> 5);

        ull g2[8][2];
        #pragma unroll
        for (int i = 0; i < 8; i++) { g2[i][0] = 0ull; g2[i][1] = 0ull; }

        #pragma unroll 1
        for (int k8 = 0; k8 < 64; k8 += 8) {
            ull gl[15];
            int gb = r0 - k8 + 57;            // in [1,120]
            #pragma unroll
            for (int m = 0; m < 15; m++) gl[m] = pk2(hb[gb + m]);
            #pragma unroll
            for (int kk = 0; kk < 8; kk++) {
                int ro = (k8 + kk) * 68 + c0 + gapc;   // even -> 8B aligned
                ull xq0 = *(const ull*)&Xs[ro];
                ull xq1 = *(const ull*)&Xs[ro + 2];
                #pragma unroll
                for (int i = 0; i < 8; i++) {
                    fma2(g2[i][0], gl[i - kk + 7], xq0);
                    fma2(g2[i][1], gl[i - kk + 7], xq1);
                }
            }
        }

        asm volatile("cp.async.wait_group 0;");
        __syncthreads();

        #pragma unroll
        for (int i = 0; i < 8; i++) {
            int row = r0 + i;
            int off = row * 64 + c0;
            float4 dv = *(const float4*)(g_delta + off_bd + off);
            float4 my = *(const float4*)&Ms[off];
            float2 t0 = up2(g2[i][0]);
            float2 t1 = up2(g2[i][1]);
            float4 myn;
            myn.x = __expf(dv.x * Ad) * (my.x - t0.x);
            myn.y = __expf(dv.y * Ad) * (my.y - t0.y);
            myn.z = __expf(dv.z * Ad) * (my.z - t1.x);
            myn.w = __expf(dv.w * Ad) * (my.w - t1.y);
            *(float4*)(out + so + p2 + off) = myn;
        }
    }
}

// ---------------------------------------------------------------------------
// K4: y = sum_n m0_new * C + u*D. 2x float4 per thread for MLP.
// ---------------------------------------------------------------------------
__global__ void __launch_bounds__(128) k_y(
        const float* __restrict__ u, const float* __restrict__ Dp,
        float* __restrict__ out) {
    int base4 = blockIdx.x * 256 + threadIdx.x;   // two slots: base4, base4+128
    const int so = NB * DM * HW;
    float4 a0 = make_float4(0.f, 0.f, 0.f, 0.f);
    float4 a1 = make_float4(0.f, 0.f, 0.f, 0.f);

    int i0 = base4, i1 = base4 + 128;
    int b0 = i0 >> 16, d0 = (i0 >> 10) & 63, q0 = i0 & 1023;
    int b1 = i1 >> 16, d1 = (i1 >> 10) & 63, q1 = i1 & 1023;
    const float4* m0 = (const float4*)(out + so + ((b0 * 3 * 64 + d0) * 16) * HW) + q0;
    const float4* C0 = (const float4*)(g_Cval + (b0 * 16) * HW) + q0;
    const float4* m1 = (const float4*)(out + so + ((b1 * 3 * 64 + d1) * 16) * HW) + q1;
    const float4* C1 = (const float4*)(g_Cval + (b1 * 16) * HW) + q1;

    #pragma unroll
    for (int nn = 0; nn < 16; nn++) {
        float4 ma = m0[nn * 1024];
        float4 ca = C0[nn * 1024];
        float4 mb = m1[nn * 1024];
        float4 cb = C1[nn * 1024];
        a0.x = fmaf(ma.x, ca.x, a0.x); a0.y = fmaf(ma.y, ca.y, a0.y);
        a0.z = fmaf(ma.z, ca.z, a0.z); a0.w = fmaf(ma.w, ca.w, a0.w);
        a1.x = fmaf(mb.x, cb.x, a1.x); a1.y = fmaf(mb.y, cb.y, a1.y);
        a1.z = fmaf(mb.z, cb.z, a1.z); a1.w = fmaf(mb.w, cb.w, a1.w);
    }
    float D0 = Dp[d0], D1 = Dp[d1];
    float4 u0 = ((const float4*)u)[i0];
    float4 u1 = ((const float4*)u)[i1];
    a0.x = fmaf(u0.x, D0, a0.x); a0.y = fmaf(u0.y, D0, a0.y);
    a0.z = fmaf(u0.z, D0, a0.z); a0.w = fmaf(u0.w, D0, a0.w);
    a1.x = fmaf(u1.x, D1, a1.x); a1.y = fmaf(u1.y, D1, a1.y);
    a1.z = fmaf(u1.z, D1, a1.z); a1.w = fmaf(u1.w, D1, a1.w);
    ((float4*)out)[i0] = a0;
    ((float4*)out)[i1] = a1;
}

// ---------------------------------------------------------------------------
extern "C" void kernel_launch(void* const* d_in, const int* in_sizes, int n_in,
                              void* d_out, int out_size) {
    const float* u     = (const float*)d_in[0];
    const float* sprev = (const float*)d_in[1];
    const float* gamma = (const float*)d_in[2];
    const float* beta  = (const float*)d_in[3];
    const float* wd    = (const float*)d_in[4];
    const float* bd    = (const float*)d_in[5];
    const float* wB    = (const float*)d_in[6];
    const float* wC    = (const float*)d_in[7];
    const float* logA  = (const float*)d_in[8];
    const float* Dp    = (const float*)d_in[9];
    const float* dt    = (const float*)d_in[10];
    float* out = (float*)d_out;

    k_prep<<<733, 256>>>(u, wd, wB, wC);
    k_conv<<<512, 128>>>(u, gamma, beta, bd, dt);
    k_update<<<4096, 128>>>(u, sprev, logA, out);
    k_y<<<1024, 128>>>(u, Dp, out);
}

// round 17
// speedup vs baseline: 1.0144x; 1.0144x over previous
#include <cuda_runtime.h>
#include <math.h>

#define HW    4096
#define DM    64
#define DS    16
#define NB    4

// Scratch (device globals; no allocation allowed)
__device__ float g_h[64];
__device__ float g_part[1024];        // 512 stat blocks x (sum, sumsq)
__device__ float g_wT[16 * 3528];     // transposed weights [chunk][icl*9+tap][98]
__device__ float g_delta[NB*DM*HW];   // 4MB
__device__ float g_Bval[NB*DS*HW];    // 1MB
__device__ float g_Cval[NB*DS*HW];    // 1MB

typedef unsigned long long ull;

__device__ __forceinline__ ull pk2(float x) {
    ull r; asm("mov.b64 %0,{%1,%1};" : "=l"(r) : "f"(x)); return r;
}
__device__ __forceinline__ ull pk(float lo, float hi) {
    ull r; asm("mov.b64 %0,{%1,%2};" : "=l"(r) : "f"(lo), "f"(hi)); return r;
}
__device__ __forceinline__ void fma2(ull &a, ull b, ull c) {
    asm("fma.rn.f32x2 %0,%1,%2,%0;" : "+l"(a) : "l"(b), "l"(c));
}
__device__ __forceinline__ float2 up2(ull a) {
    float2 v; asm("mov.b64 {%0,%1},%2;" : "=f"(v.x), "=f"(v.y) : "l"(a)); return v;
}

// ---------------------------------------------------------------------------
// K0 (fused prep): blocks 0..511 = GroupNorm partial sums;
// blocks 512..732 = weight transpose (+ h table in block 512).
// ---------------------------------------------------------------------------
__global__ void __launch_bounds__(256) k_prep(
        const float* __restrict__ u,
        const float* __restrict__ wd,
        const float* __restrict__ wB,
        const float* __restrict__ wC) {
    int blk = blockIdx.x;
    if (blk < 512) {
        int bg = blk >> 5, seg = blk & 31;
        const float4* base = (const float4*)(u + bg * 65536 + seg * 2048);
        float s = 0.f, s2 = 0.f;
        #pragma unroll
        for (int i = threadIdx.x; i < 512; i += 256) {
            float4 v = base[i];
            s += v.x + v.y + v.z + v.w;
            s2 = fmaf(v.x, v.x, s2); s2 = fmaf(v.y, v.y, s2);
            s2 = fmaf(v.z, v.z, s2); s2 = fmaf(v.w, v.w, s2);
        }
        for (int o = 16; o; o >>= 1) {
            s  += __shfl_down_sync(0xFFFFFFFFu, s,  o);
            s2 += __shfl_down_sync(0xFFFFFFFFu, s2, o);
        }
        __shared__ float ss[8], ss2[8];
        int w = threadIdx.x >> 5, l = threadIdx.x & 31;
        if (l == 0) { ss[w] = s; ss2[w] = s2; }
        __syncthreads();
        if (threadIdx.x == 0) {
            float S = 0.f, S2 = 0.f;
            #pragma unroll
            for (int i = 0; i < 8; i++) { S += ss[i]; S2 += ss2[i]; }
            g_part[blk * 2]     = S;
            g_part[blk * 2 + 1] = S2;
        }
    } else {
        int wb = blk - 512;
        if (wb == 0 && threadIdx.x < 64) {
            int n = threadIdx.x;
            double acc = 0.0;
            for (int m = 1; m < 32; m++) {
                double km = 2.0 * 3.141592653589793238 * (double)m / 64.0;
                acc += km * sin(km * (double)n);
            }
            g_h[n] = (float)(-acc * 2.0 / 64.0);
        }
        int idx = wb * 256 + threadIdx.x;
        if (idx >= 16 * 3528) return;
        int chunk = idx / 3528;
        int r2 = idx - chunk * 3528;
        int row = r2 / 98;            // icl*9 + tap
        int oc  = r2 - row * 98;
        int icl = row / 9, tap = row - icl * 9;
        int ic  = chunk * 4 + icl;
        float v = 0.f;
        if (oc < 64)      v = wd[oc * 576 + ic * 9 + tap];
        else if (oc < 80) v = wB[(oc - 64) * 576 + ic * 9 + tap];
        else if (oc < 96) v = wC[(oc - 80) * 576 + ic * 9 + tap];
        g_wT[idx] = v;
    }
}

// ---------------------------------------------------------------------------
// K2: fused GroupNorm + circular 3x3 convs, with icl-pipelined x loads.
// ---------------------------------------------------------------------------
__global__ void __launch_bounds__(128, 4) k_conv(
        const float* __restrict__ u,
        const float* __restrict__ gamma, const float* __restrict__ beta,
        const float* __restrict__ bd, const float* __restrict__ dtp) {
    __shared__ float ws2[2][3528];       // 28.2KB [buf][(icl*9+tap)*98 + oc]
    __shared__ float xs2[2][408];        // 3.3KB  [buf][(icl*3+rr)*34 + j]
    __shared__ float cs_scale[64], cs_shift[64];

    int bx = blockIdx.x;
    int b  = bx >> 7;
    int t  = bx & 127;
    int y  = t >> 1;
    int x0 = (t & 1) * 32;

    int tid = threadIdx.x;
    int ocg = tid >> 3;            // 0..15
    int pxg = tid & 7;             // 0..7
    int oc0 = ocg * 6;
    int px0 = pxg * 4;

    if (tid < 64) {
        int bg = b * 4 + (tid >> 4);
        float S = 0.f, S2 = 0.f;
        #pragma unroll
        for (int i = 0; i < 32; i++) {
            S  += g_part[(bg * 32 + i) * 2];
            S2 += g_part[(bg * 32 + i) * 2 + 1];
        }
        float mu  = S  * (1.f / 65536.f);
        float var = S2 * (1.f / 65536.f) - mu * mu;
        float rs = rsqrtf(var + 1e-5f) * gamma[tid];
        cs_scale[tid] = rs;
        cs_shift[tid] = beta[tid] - mu * rs;
    }
    __syncthreads();

    int s_row[4], s_j[4], s_icl[4], s_gy[4], s_gx[4];
    bool s_ok[4];
    #pragma unroll
    for (int s = 0; s < 4; s++) {
        int idx = tid + 128 * s;
        s_ok[s] = idx < 408;
        int row = idx / 34;
        int j   = idx - row * 34;
        if (!s_ok[s]) { row = 0; j = 0; }
        int icl = row / 3;
        int rr  = row - icl * 3;
        s_row[s] = row; s_j[s] = j; s_icl[s] = icl;
        s_gy[s] = (y + rr - 1) & 63;
        s_gx[s] = (x0 - 1 + j) & 63;
    }

    unsigned ws_sm = (unsigned)__cvta_generic_to_shared(ws2);

    {
        const float4* wsrc = (const float4*)g_wT;
        #pragma unroll
        for (int s = 0; s < 7; s++) {
            int i = tid + 128 * s;
            if (i < 882) {
                unsigned dst = ws_sm + i * 16;
                asm volatile("cp.async.cg.shared.global [%0], [%1], 16;"
                             :: "r"(dst), "l"(wsrc + i));
            }
        }
        asm volatile("cp.async.commit_group;");
    }
    {
        #pragma unroll
        for (int s = 0; s < 4; s++) {
            if (s_ok[s]) {
                int ic = s_icl[s];
                float v = u[((b * 64 + ic) * 64 + s_gy[s]) * 64 + s_gx[s]];
                xs2[0][s_row[s] * 34 + s_j[s]] = fmaf(v, cs_scale[ic], cs_shift[ic]);
            }
        }
    }
    asm volatile("cp.async.wait_group 0;");
    __syncthreads();

    ull acc[3][4];
    #pragma unroll
    for (int p = 0; p < 3; p++)
        #pragma unroll
        for (int q = 0; q < 4; q++) acc[p][q] = 0ull;

    #pragma unroll 1
    for (int c = 0; c < 16; c++) {
        float xstage[4];
        if (c < 15) {
            const float4* wsrc = (const float4*)g_wT + (c + 1) * 882;
            unsigned wdst = ws_sm + ((c + 1) & 1) * 14112;
            #pragma unroll
            for (int s = 0; s < 7; s++) {
                int i = tid + 128 * s;
                if (i < 882) {
                    asm volatile("cp.async.cg.shared.global [%0], [%1], 16;"
                                 :: "r"(wdst + i * 16), "l"(wsrc + i));
                }
            }
            asm volatile("cp.async.commit_group;");
            #pragma unroll
            for (int s = 0; s < 4; s++) {
                if (s_ok[s]) {
                    int ic = (c + 1) * 4 + s_icl[s];
                    float v = u[((b * 64 + ic) * 64 + s_gy[s]) * 64 + s_gx[s]];
                    xstage[s] = fmaf(v, cs_scale[ic], cs_shift[ic]);
                }
            }
        }

        const float* wsb = ws2[c & 1];
        const float* xsb = xs2[c & 1];

        // parity-buffered x-patch prefetch across icl
        float2 xb[2][3][3];
        {
            const float* xp = xsb + px0;      // icl = 0
            #pragma unroll
            for (int rr = 0; rr < 3; rr++) {
                xb[0][rr][0] = *(const float2*)(xp + rr * 34);
                xb[0][rr][1] = *(const float2*)(xp + rr * 34 + 2);
                xb[0][rr][2] = *(const float2*)(xp + rr * 34 + 4);
            }
        }
        #pragma unroll
        for (int icl = 0; icl < 4; icl++) {
            int cb = icl & 1;
            if (icl < 3) {
                const float* xp = xsb + (icl + 1) * 102 + px0;
                #pragma unroll
                for (int rr = 0; rr < 3; rr++) {
                    xb[cb ^ 1][rr][0] = *(const float2*)(xp + rr * 34);
                    xb[cb ^ 1][rr][1] = *(const float2*)(xp + rr * 34 + 2);
                    xb[cb ^ 1][rr][2] = *(const float2*)(xp + rr * 34 + 4);
                }
            }
            ull P[3][6];
            #pragma unroll
            for (int rr = 0; rr < 3; rr++) {
                P[rr][0] = pk2(xb[cb][rr][0].x); P[rr][1] = pk2(xb[cb][rr][0].y);
                P[rr][2] = pk2(xb[cb][rr][1].x); P[rr][3] = pk2(xb[cb][rr][1].y);
                P[rr][4] = pk2(xb[cb][rr][2].x); P[rr][5] = pk2(xb[cb][rr][2].y);
            }
            #pragma unroll
            for (int dy = 0; dy < 3; dy++) {
                #pragma unroll
                for (int dx = 0; dx < 3; dx++) {
                    const float* row = wsb + (icl * 9 + dy * 3 + dx) * 98 + oc0;
                    ull w01 = *(const ull*)(row);
                    ull w23 = *(const ull*)(row + 2);
                    ull w45 = *(const ull*)(row + 4);
                    ull pa = P[dy][dx];
                    ull pb = P[dy][dx + 1];
                    ull pc = P[dy][dx + 2];
                    ull pd = P[dy][dx + 3];
                    fma2(acc[0][0], w01, pa); fma2(acc[0][1], w01, pb);
                    fma2(acc[0][2], w01, pc); fma2(acc[0][3], w01, pd);
                    fma2(acc[1][0], w23, pa); fma2(acc[1][1], w23, pb);
                    fma2(acc[1][2], w23, pc); fma2(acc[1][3], w23, pd);
                    fma2(acc[2][0], w45, pa); fma2(acc[2][1], w45, pb);
                    fma2(acc[2][2], w45, pc); fma2(acc[2][3], w45, pd);
                }
            }
        }

        if (c < 15) {
            float* xdst = xs2[(c + 1) & 1];
            #pragma unroll
            for (int s = 0; s < 4; s++)
                if (s_ok[s]) xdst[s_row[s] * 34 + s_j[s]] = xstage[s];
            asm volatile("cp.async.wait_group 0;");
        }
        __syncthreads();
    }

    float dtv = __ldg(dtp);
    int pbase = y * 64 + x0 + px0;

    #pragma unroll
    for (int p = 0; p < 3; p++) {
        #pragma unroll
        for (int half = 0; half < 2; half++) {
            int oc = oc0 + 2 * p + half;
            float av[4];
            #pragma unroll
            for (int q = 0; q < 4; q++) {
                float2 v = up2(acc[p][q]);
                av[q] = half ? v.y : v.x;
            }
            if (oc < 64) {
                float bias = bd[oc] + dtv;
                float4 o4;
                float* pv = &o4.x;
                #pragma unroll
                for (int q = 0; q < 4; q++) {
                    float v = av[q] + bias;
                    float sp = (v > 0.f) ? (v + log1pf(expf(-v))) : log1pf(expf(v));
                    pv[q] = fminf(fmaxf(sp, 1e-4f), 5.0f);
                }
                *(float4*)(g_delta + (b * 64 + oc) * HW + pbase) = o4;
            } else if (oc < 80) {
                *(float4*)(g_Bval + (b * 16 + (oc - 64)) * HW + pbase) =
                    make_float4(av[0], av[1], av[2], av[3]);
            } else {
                *(float4*)(g_Cval + (b * 16 + (oc - 80)) * HW + pbase) =
                    make_float4(av[0], av[1], av[2], av[3]);
            }
        }
    }
}

// ---------------------------------------------------------------------------
// K3: circulant matmuls, software-pipelined X loads in both phases.
// ---------------------------------------------------------------------------
__global__ void __launch_bounds__(128, 5) k_update(
        const float* __restrict__ u, const float* __restrict__ sprev,
        const float* __restrict__ logA, float* __restrict__ out) {
    __shared__ float Xs[64 * 68];    // X[r][c] at r*68 + c + 2*(c>>5)  17.4KB
    __shared__ float Ms[4096];       // staging: mx then my             16KB
    __shared__ float hb[144];        // h[i mod 64]

    int tid = threadIdx.x;
    int bp  = blockIdx.x;            // b*1024 + d*16 + n
    int b = bp >> 10, d = (bp >> 4) & 63, n = bp & 15;

    int p0 = (((b * 3 + 0) * 64 + d) * 16 + n) * HW;
    int p1 = p0 + 64 * 16 * HW;
    int p2 = p1 + 64 * 16 * HW;
    const float4* m0p4 = (const float4*)(sprev + p0);

    unsigned ms_sm = (unsigned)__cvta_generic_to_shared(Ms);

    {
        const float4* mxp = (const float4*)(sprev + p1);
        #pragma unroll
        for (int s = 0; s < 8; s++) {
            int i = tid + 128 * s;
            asm volatile("cp.async.cg.shared.global [%0], [%1], 16;"
                         :: "r"(ms_sm + i * 16), "l"(mxp + i));
        }
        asm volatile("cp.async.commit_group;");
    }

    #pragma unroll
    for (int s = 0; s < 8; s++) {
        int l4 = tid + 128 * s;              // < 1024
        float4 v = m0p4[l4];
        int idx = l4 * 4;
        int r = idx >> 6, cc = idx & 63;
        float* xsp = &Xs[r * 68 + cc + 2 * (cc >> 5)];
        *(float2*)xsp       = make_float2(v.x, v.y);
        *(float2*)(xsp + 2) = make_float2(v.z, v.w);
    }
    for (int i = tid; i < 144; i += 128) hb[i] = g_h[i & 63];
    __syncthreads();

    float Ad = -expf(__ldg(&logA[d * 16 + n]));
    int off_bd = (b * 64 + d) * HW;
    int off_bn = (b * 16 + n) * HW;
    const int so = NB * DM * HW;

    // ===== Phase 1: Gx[r][c] = sum_k X[r][k] h[c-k], 4 rows x 8 cols =====
    {
        int rg = tid >> 3, cg = tid & 7;    // rg 0..15, cg 0..7
        int r0 = rg * 4, c0 = cg * 8;
        int gap2 = 2 * (c0 >> 5);

        ull a[2][8];
        #pragma unroll
        for (int p = 0; p < 2; p++)
            #pragma unroll
            for (int j = 0; j < 8; j++) a[p][j] = 0ull;

        float2 xr[2][4];
        #pragma unroll
        for (int i = 0; i < 4; i++)
            xr[0][i] = *(const float2*)&Xs[(r0 + i) * 68];   // k8=0, kk2=0

        #pragma unroll 1
        for (int k8 = 0; k8 < 64; k8 += 8) {
            ull hl[15];
            int hbase = c0 - k8 + 57;       // in [1,113]
            #pragma unroll
            for (int m = 0; m < 15; m++) hl[m] = pk2(hb[hbase + m]);
            int gk = 2 * (k8 >> 5);
            #pragma unroll
            for (int kk2 = 0; kk2 < 4; kk2++) {
                int cb = kk2 & 1;
                // prefetch next kk2 group (or next k8's first group)
                if (!((k8 == 56) && (kk2 == 3))) {
                    int xo_n;
                    if (kk2 < 3) xo_n = k8 + (kk2 + 1) * 2 + gk;
                    else { int nk8 = k8 + 8; xo_n = nk8 + 2 * (nk8 >> 5); }
                    #pragma unroll
                    for (int i = 0; i < 4; i++)
                        xr[cb ^ 1][i] = *(const float2*)&Xs[(r0 + i) * 68 + xo_n];
                }
                float2 x0v = xr[cb][0], x1v = xr[cb][1];
                float2 x2v = xr[cb][2], x3v = xr[cb][3];
                {   // kk = 2*kk2
                    int kk = kk2 * 2;
                    ull x01 = pk(x0v.x, x1v.x), x23 = pk(x2v.x, x3v.x);
                    #pragma unroll
                    for (int j = 0; j < 8; j++) {
                        fma2(a[0][j], x01, hl[j - kk + 7]);
                        fma2(a[1][j], x23, hl[j - kk + 7]);
                    }
                }
                {   // kk = 2*kk2+1
                    int kk = kk2 * 2 + 1;
                    ull x01 = pk(x0v.y, x1v.y), x23 = pk(x2v.y, x3v.y);
                    #pragma unroll
                    for (int j = 0; j < 8; j++) {
                        fma2(a[0][j], x01, hl[j - kk + 7]);
                        fma2(a[1][j], x23, hl[j - kk + 7]);
                    }
                }
            }
        }

        asm volatile("cp.async.wait_group 0;");
        __syncthreads();

        #pragma unroll
        for (int i = 0; i < 4; i++) {
            int row = r0 + i;
            int off = row * 64 + c0;
            float4 dv0 = *(const float4*)(g_delta + off_bd + off);
            float4 dv1 = *(const float4*)(g_delta + off_bd + off + 4);
            float4 uv0 = *(const float4*)(u + off_bd + off);
            float4 uv1 = *(const float4*)(u + off_bd + off + 4);
            float4 bv0 = *(const float4*)(g_Bval + off_bn + off);
            float4 bv1 = *(const float4*)(g_Bval + off_bn + off + 4);
            float4 mx0 = *(const float4*)&Ms[off];
            float4 mx1 = *(const float4*)&Ms[off + 4];
            float dd[8] = { dv0.x, dv0.y, dv0.z, dv0.w, dv1.x, dv1.y, dv1.z, dv1.w };
            float uu[8] = { uv0.x, uv0.y, uv0.z, uv0.w, uv1.x, uv1.y, uv1.z, uv1.w };
            float bb[8] = { bv0.x, bv0.y, bv0.z, bv0.w, bv1.x, bv1.y, bv1.z, bv1.w };
            float mx[8] = { mx0.x, mx0.y, mx0.z, mx0.w, mx1.x, mx1.y, mx1.z, mx1.w };
            float m0n[8], mxn[8];
            #pragma unroll
            for (int j = 0; j < 8; j++) {
                float2 tt = up2(a[i >> 1][j]);
                float gx = (i & 1) ? tt.y : tt.x;
                float m0v = Xs[row * 68 + c0 + j + gap2];
                float Ab = __expf(dd[j] * Ad);
                m0n[j] = fmaf(Ab, m0v, dd[j] * bb[j] * uu[j]);
                mxn[j] = Ab * (mx[j] - gx);
            }
            *(float4*)(out + so + p0 + off)     = make_float4(m0n[0], m0n[1], m0n[2], m0n[3]);
            *(float4*)(out + so + p0 + off + 4) = make_float4(m0n[4], m0n[5], m0n[6], m0n[7]);
            *(float4*)(out + so + p1 + off)     = make_float4(mxn[0], mxn[1], mxn[2], mxn[3]);
            *(float4*)(out + so + p1 + off + 4) = make_float4(mxn[4], mxn[5], mxn[6], mxn[7]);
        }
    }

    __syncthreads();
    {
        const float4* myp = (const float4*)(sprev + p2);
        #pragma unroll
        for (int s = 0; s < 8; s++) {
            int i = tid + 128 * s;
            asm volatile("cp.async.cg.shared.global [%0], [%1], 16;"
                         :: "r"(ms_sm + i * 16), "l"(myp + i));
        }
        asm volatile("cp.async.commit_group;");
    }

    // ===== Phase 2: Gy[r][c] = sum_k h[r-k] X[k][c], 8 rows x 4 cols =====
    {
        int rg2 = tid >> 4, cg2 = tid & 15;   // rg2 0..7, cg2 0..15
        int r0 = rg2 * 8, c0 = cg2 * 4;
        int gapc = 2 * (c0 >> 5);

        ull g2[8][2];
        #pragma unroll
        for (int i = 0; i < 8; i++) { g2[i][0] = 0ull; g2[i][1] = 0ull; }

        ull xq[2][2];
        {
            int ro0 = c0 + gapc;              // k = 0
            xq[0][0] = *(const ull*)&Xs[ro0];
            xq[0][1] = *(const ull*)&Xs[ro0 + 2];
        }

        #pragma unroll 1
        for (int k8 = 0; k8 < 64; k8 += 8) {
            ull gl[15];
            int gb = r0 - k8 + 57;            // in [1,120]
            #pragma unroll
            for (int m = 0; m < 15; m++) gl[m] = pk2(hb[gb + m]);
            #pragma unroll
            for (int kk = 0; kk < 8; kk++) {
                int cb = kk & 1;
                if (!((k8 == 56) && (kk == 7))) {
                    int ro = (k8 + kk + 1) * 68 + c0 + gapc;
                    xq[cb ^ 1][0] = *(const ull*)&Xs[ro];
                    xq[cb ^ 1][1] = *(const ull*)&Xs[ro + 2];
                }
                ull xq0 = xq[cb][0], xq1 = xq[cb][1];
                #pragma unroll
                for (int i = 0; i < 8; i++) {
                    fma2(g2[i][0], gl[i - kk + 7], xq0);
                    fma2(g2[i][1], gl[i - kk + 7], xq1);
                }
            }
        }

        asm volatile("cp.async.wait_group 0;");
        __syncthreads();

        #pragma unroll
        for (int i = 0; i < 8; i++) {
            int row = r0 + i;
            int off = row * 64 + c0;
            float4 dv = *(const float4*)(g_delta + off_bd + off);
            float4 my = *(const float4*)&Ms[off];
            float2 t0 = up2(g2[i][0]);
            float2 t1 = up2(g2[i][1]);
            float4 myn;
            myn.x = __expf(dv.x * Ad) * (my.x - t0.x);
            myn.y = __expf(dv.y * Ad) * (my.y - t0.y);
            myn.z = __expf(dv.z * Ad) * (my.z - t1.x);
            myn.w = __expf(dv.w * Ad) * (my.w - t1.y);
            *(float4*)(out + so + p2 + off) = myn;
        }
    }
}

// ---------------------------------------------------------------------------
// K4: y[b,d,p] = sum_n m0_new[b,d,n,p] * C_val[b,n,p] + u*D[d]  (float4)
// ---------------------------------------------------------------------------
__global__ void __launch_bounds__(128) k_y(
        const float* __restrict__ u, const float* __restrict__ Dp,
        float* __restrict__ out) {
    int idx4 = blockIdx.x * 128 + threadIdx.x;   // < 262144
    int b = idx4 >> 16;
    int d = (idx4 >> 10) & 63;
    int p4 = idx4 & 1023;
    const int so = NB * DM * HW;
    const float4* m0n = (const float4*)(out + so + ((b * 3 * 64 + d) * 16) * HW) + p4;
    const float4* Cv  = (const float4*)(g_Cval + (b * 16) * HW) + p4;
    float4 a = make_float4(0.f, 0.f, 0.f, 0.f);
    #pragma unroll
    for (int nn = 0; nn < 16; nn++) {
        float4 m = m0n[nn * 1024];
        float4 c = Cv[nn * 1024];
        a.x = fmaf(m.x, c.x, a.x); a.y = fmaf(m.y, c.y, a.y);
        a.z = fmaf(m.z, c.z, a.z); a.w = fmaf(m.w, c.w, a.w);
    }
    float Dd = Dp[d];
    float4 uv = ((const float4*)u)[idx4];
    a.x = fmaf(uv.x, Dd, a.x); a.y = fmaf(uv.y, Dd, a.y);
    a.z = fmaf(uv.z, Dd, a.z); a.w = fmaf(uv.w, Dd, a.w);
    ((float4*)out)[idx4] = a;
}

// ---------------------------------------------------------------------------
extern "C" void kernel_launch(void* const* d_in, const int* in_sizes, int n_in,
                              void* d_out, int out_size) {
    const float* u     = (const float*)d_in[0];
    const float* sprev = (const float*)d_in[1];
    const float* gamma = (const float*)d_in[2];
    const float* beta  = (const float*)d_in[3];
    const float* wd    = (const float*)d_in[4];
    const float* bd    = (const float*)d_in[5];
    const float* wB    = (const float*)d_in[6];
    const float* wC    = (const float*)d_in[7];
    const float* logA  = (const float*)d_in[8];
    const float* Dp    = (const float*)d_in[9];
    const float* dt    = (const float*)d_in[10];
    float* out = (float*)d_out;

    k_prep<<<733, 256>>>(u, wd, wB, wC);
    k_conv<<<512, 128>>>(u, gamma, beta, bd, dt);
    k_update<<<4096, 128>>>(u, sprev, logA, out);
    k_y<<<2048, 128>>>(u, Dp, out);
}